// round 4
// baseline (speedup 1.0000x reference)
#include <cuda_runtime.h>

// ESN recurrence on GB300 — barrier-free step exchange via tagged 64-bit words
// with memory-model-correct acquire/release ops (CUTLASS-barrier style).
// Each x element is published as {tag<<32 | f32bits} in ONE 8-byte word:
// tag match <=> value valid. No atomics, no global barrier, no fences.

#define H        1024
#define T        50000
#define WASHOUT  200
#define NOUT     (T - WASHOUT)   // 49800
#define B        128             // CTAs (<=148 SMs -> co-resident, spin-safe)
#define R        (H / B)         // 8 rows per CTA
#define THREADS  256             // 8 warps, 1 warp per row
#define NPART    (B * R)         // 1024 partial rows

// Persistent device state
__device__ unsigned long long g_xt[2][H];        // tagged state, double-buffered
__device__ float    g_coef[H];                    // coef[mask[h]] = w_out[h]
__device__ unsigned g_epoch;                      // bumped per replay -> unique tags
__device__ float    g_part[(size_t)NPART * NOUT]; // per-row readout partials

static __device__ __forceinline__ unsigned long long pack_tv(unsigned tag, float v) {
    return ((unsigned long long)tag << 32) | (unsigned long long)__float_as_uint(v);
}

static __device__ __forceinline__ unsigned long long ld_acq(const unsigned long long* p) {
    unsigned long long v;
    asm volatile("ld.acquire.gpu.global.u64 %0, [%1];" : "=l"(v) : "l"(p) : "memory");
    return v;
}

static __device__ __forceinline__ void st_rel(unsigned long long* p, unsigned long long v) {
    asm volatile("st.release.gpu.global.u64 [%0], %1;" :: "l"(p), "l"(v) : "memory");
}

// ---------------------------------------------------------------------------
// Prologue: bump epoch, publish x0 (zeros, tag=base), build coef scatter.
// Mask dtype probed in parallel: an int64 permutation of 0..1023 has zero
// high-words at every odd int32 slot (512 zeros); int32 has <=1 zero there.
// ---------------------------------------------------------------------------
__global__ void esn_prologue(const float* __restrict__ w_out,
                             const void* __restrict__ mask_raw) {
    const int* m32 = (const int*)mask_raw;
    const int t = threadIdx.x;                    // 0..1023

    int is64 = __syncthreads_count(((t & 1) != 0) && (m32[t] == 0)) >= 256;
    if (t == 0) g_epoch = g_epoch + 1u;
    __syncthreads();
    const unsigned base = g_epoch * (unsigned)(T + 2);

    int idx;
    if (is64) idx = (int)((const long long*)mask_raw)[t];  // 8KB view
    else      idx = m32[t];                                // 4KB view
    g_coef[idx & 1023] = w_out[t];                // masked: can never fault
    g_xt[0][t] = pack_tv(base, 0.0f);             // x_0 = 0, tag = base
}

// ---------------------------------------------------------------------------
// Main persistent kernel. Warp w of CTA c owns row c*8+w; its 1024 weights
// live in 32 registers/lane. Per step: acquire-poll 4 tagged words/thread,
// stage to SMEM, sync, reg-resident dot, shfl reduce, tanh, release-publish.
// ---------------------------------------------------------------------------
__global__ void __launch_bounds__(THREADS, 1)
esn_main(const float* __restrict__ u,
         const float* __restrict__ w_in,
         const float* __restrict__ w_res) {
    __shared__ float s_x[H];                      // 4 KB staging

    const int tid  = threadIdx.x;
    const int warp = tid >> 5;
    const int lane = tid & 31;
    const int row  = blockIdx.x * R + warp;

    // Weights into registers: lane l holds cols 4l+128j, j=0..7 (32 floats)
    float4 wreg[8];
    {
        const float4* wr = reinterpret_cast<const float4*>(w_res + (size_t)row * H);
        #pragma unroll
        for (int j = 0; j < 8; ++j)
            wreg[j] = __ldg(wr + lane + 32 * j);
    }
    const float my_win  = w_in[row];
    const float my_coef = g_coef[row];
    const unsigned base = g_epoch * (unsigned)(T + 2);
    float* part_row = &g_part[(size_t)row * NOUT];

    for (int k = 0; k < T; ++k) {
        const float uk = __ldg(u + k);

        // ---- acquire-poll this thread's 4 tagged words ---------------------
        const unsigned want = base + (unsigned)k;
        const unsigned long long* gx = &g_xt[k & 1][tid << 2];
        unsigned long long v0, v1, v2, v3;
        for (;;) {
            v0 = ld_acq(gx + 0);
            v1 = ld_acq(gx + 1);
            v2 = ld_acq(gx + 2);
            v3 = ld_acq(gx + 3);
            if ((unsigned)(v0 >> 32) == want && (unsigned)(v1 >> 32) == want &&
                (unsigned)(v2 >> 32) == want && (unsigned)(v3 >> 32) == want)
                break;
        }
        float4 xv;
        xv.x = __uint_as_float((unsigned)v0);
        xv.y = __uint_as_float((unsigned)v1);
        xv.z = __uint_as_float((unsigned)v2);
        xv.w = __uint_as_float((unsigned)v3);
        reinterpret_cast<float4*>(s_x)[tid] = xv;
        __syncthreads();                          // staging complete

        // ---- register-weight dot product against SMEM x --------------------
        const float4* xr = reinterpret_cast<const float4*>(s_x);
        float acc = 0.0f;
        #pragma unroll
        for (int j = 0; j < 8; ++j) {
            float4 xb = xr[lane + 32 * j];
            acc = fmaf(wreg[j].x, xb.x, acc);
            acc = fmaf(wreg[j].y, xb.y, acc);
            acc = fmaf(wreg[j].z, xb.z, acc);
            acc = fmaf(wreg[j].w, xb.w, acc);
        }
        #pragma unroll
        for (int off = 16; off > 0; off >>= 1)
            acc += __shfl_xor_sync(0xffffffffu, acc, off);

        if (lane == 0) {
            const float val = tanhf(fmaf(my_win, uk, acc));
            st_rel(&g_xt[(k + 1) & 1][row], pack_tv(want + 1u, val)); // publish
            if (k >= WASHOUT)
                part_row[k - WASHOUT] = val * my_coef;                // readout
        }
        __syncthreads();                          // close the step (safety)
    }
}

// ---------------------------------------------------------------------------
// Finalize: deterministic fixed-order reduction of 1024 per-row partials.
// ---------------------------------------------------------------------------
__global__ void esn_finalize(float* __restrict__ out) {
    int t = blockIdx.x * blockDim.x + threadIdx.x;
    if (t < NOUT) {
        float s = 0.0f;
        #pragma unroll 8
        for (int r = 0; r < NPART; ++r)
            s += g_part[(size_t)r * NOUT + t];    // coalesced across threads
        out[t] = s;
    }
}

// ---------------------------------------------------------------------------
// Inputs (metadata order): u[50000] f32, w_in[1024] f32, w_res[1024*1024] f32,
// w_out[1024] f32, w_out_mask[1024] int (32/64 probed). Output: 49800 f32.
// ---------------------------------------------------------------------------
extern "C" void kernel_launch(void* const* d_in, const int* in_sizes, int n_in,
                              void* d_out, int out_size) {
    const float* u     = (const float*)d_in[0];
    const float* w_in  = (const float*)d_in[1];
    const float* w_res = (const float*)d_in[2];
    const float* w_out = (const float*)d_in[3];
    const void*  mask  = d_in[4];
    float*       out   = (float*)d_out;

    esn_prologue<<<1, 1024>>>(w_out, mask);
    esn_main<<<B, THREADS>>>(u, w_in, w_res);
    esn_finalize<<<(NOUT + 255) / 256, 256>>>(out);
}

// round 5
// speedup vs baseline: 1.6494x; 1.6494x over previous
#include <cuda_runtime.h>

// ESN recurrence on GB300 — per-producer-CTA flag exchange (grid.sync-style
// release/acquire chain), weak read-once data, epoch-tagged flags (no resets).

#define H        1024
#define T        50000
#define WASHOUT  200
#define NOUT     (T - WASHOUT)   // 49800
#define B        128             // CTAs (<=148 SMs -> co-resident, spin-safe)
#define R        (H / B)         // 8 rows per CTA
#define THREADS  256             // 8 warps, 1 warp per row
#define NPART    (B * R)         // 1024 partial rows
#define FPAD     32              // flag padding: 32 u32 = 128B line per flag

// Persistent device state
__device__ float    g_x[2][H];                    // double-buffered state
__device__ unsigned g_flag[2][B][FPAD];           // per-CTA step flags (tagged)
__device__ float    g_coef[H];                    // coef[mask[h]] = w_out[h]
__device__ unsigned g_epoch;                      // bumped per replay
__device__ float    g_part[(size_t)NPART * NOUT]; // per-row readout partials

static __device__ __forceinline__ unsigned ld_acq_u32(const unsigned* p) {
    unsigned v;
    asm volatile("ld.acquire.gpu.global.u32 %0, [%1];" : "=r"(v) : "l"(p) : "memory");
    return v;
}
static __device__ __forceinline__ void st_rel_u32(unsigned* p, unsigned v) {
    asm volatile("st.release.gpu.global.u32 [%0], %1;" :: "l"(p), "r"(v) : "memory");
}
static __device__ __forceinline__ void st_cg_f32(float* p, float v) {
    asm volatile("st.global.cg.f32 [%0], %1;" :: "l"(p), "f"(v) : "memory");
}
static __device__ __forceinline__ float4 ld_cg_f4(const float4* p) {
    float4 v;
    asm volatile("ld.global.cg.v4.f32 {%0,%1,%2,%3}, [%4];"
                 : "=f"(v.x), "=f"(v.y), "=f"(v.z), "=f"(v.w) : "l"(p));
    return v;
}

// ---------------------------------------------------------------------------
// Prologue: bump epoch, publish x0 = 0 with step-0 flags, build coef scatter.
// Mask dtype probed in parallel (int64 has >=512 zero odd int32 slots).
// ---------------------------------------------------------------------------
__global__ void esn_prologue(const float* __restrict__ w_out,
                             const void* __restrict__ mask_raw) {
    const int* m32 = (const int*)mask_raw;
    const int t = threadIdx.x;                    // 0..1023

    int is64 = __syncthreads_count(((t & 1) != 0) && (m32[t] == 0)) >= 256;
    if (t == 0) g_epoch = g_epoch + 1u;
    __syncthreads();
    const unsigned base = g_epoch * (unsigned)(T + 2);

    int idx;
    if (is64) idx = (int)((const long long*)mask_raw)[t];
    else      idx = m32[t];
    g_coef[idx & 1023] = w_out[t];
    g_x[0][t] = 0.0f;
    if (t < B) g_flag[0][t][0] = base;            // step-0 data ready
}

// ---------------------------------------------------------------------------
// Main persistent kernel. Warp w of CTA c owns row c*8+w (weights in regs).
// Per step:
//   thread t acquire-polls flag of producer CTA t/2 (its float4's producer),
//   loads its float4 weak .cg, stages to SMEM, bar,
//   reg-weight dot (4 accumulators), shfl reduce, tanh,
//   lane0 stores x slice .cg, bar, thread0 release-stores this CTA's flag.
// ---------------------------------------------------------------------------
__global__ void __launch_bounds__(THREADS, 1)
esn_main(const float* __restrict__ u,
         const float* __restrict__ w_in,
         const float* __restrict__ w_res) {
    __shared__ float s_x[H];                      // 4 KB staging

    const int tid  = threadIdx.x;
    const int warp = tid >> 5;
    const int lane = tid & 31;
    const int cta  = blockIdx.x;
    const int row  = cta * R + warp;

    // Weights into registers: lane l holds cols 4l+128j, j=0..7 (32 floats)
    float4 wreg[8];
    {
        const float4* wr = reinterpret_cast<const float4*>(w_res + (size_t)row * H);
        #pragma unroll
        for (int j = 0; j < 8; ++j)
            wreg[j] = __ldg(wr + lane + 32 * j);
    }
    const float my_win  = w_in[row];
    const float my_coef = g_coef[row];
    const unsigned base = g_epoch * (unsigned)(T + 2);
    float* part_row = &g_part[(size_t)row * NOUT];

    const unsigned* myflag[2] = { &g_flag[0][tid >> 1][0], &g_flag[1][tid >> 1][0] };

    for (int k = 0; k < T; ++k) {
        const float uk = __ldg(u + k);
        const unsigned want = base + (unsigned)k;
        const int buf = k & 1;

        // ---- acquire-poll the one flag guarding this thread's float4 ------
        while (ld_acq_u32(myflag[buf]) != want) { }

        // ---- load own float4 (weak, L2) and stage to SMEM ------------------
        float4 xv = ld_cg_f4(reinterpret_cast<const float4*>(g_x[buf]) + tid);
        reinterpret_cast<float4*>(s_x)[tid] = xv;
        __syncthreads();                          // all 1024 values staged

        // ---- register-weight dot product (4 accumulators) ------------------
        const float4* xr = reinterpret_cast<const float4*>(s_x);
        float a0 = 0.f, a1 = 0.f, a2 = 0.f, a3 = 0.f;
        #pragma unroll
        for (int j = 0; j < 8; j += 4) {
            float4 x0 = xr[lane + 32 * (j + 0)];
            float4 x1 = xr[lane + 32 * (j + 1)];
            float4 x2 = xr[lane + 32 * (j + 2)];
            float4 x3 = xr[lane + 32 * (j + 3)];
            a0 = fmaf(wreg[j+0].x, x0.x, a0); a0 = fmaf(wreg[j+0].y, x0.y, a0);
            a0 = fmaf(wreg[j+0].z, x0.z, a0); a0 = fmaf(wreg[j+0].w, x0.w, a0);
            a1 = fmaf(wreg[j+1].x, x1.x, a1); a1 = fmaf(wreg[j+1].y, x1.y, a1);
            a1 = fmaf(wreg[j+1].z, x1.z, a1); a1 = fmaf(wreg[j+1].w, x1.w, a1);
            a2 = fmaf(wreg[j+2].x, x2.x, a2); a2 = fmaf(wreg[j+2].y, x2.y, a2);
            a2 = fmaf(wreg[j+2].z, x2.z, a2); a2 = fmaf(wreg[j+2].w, x2.w, a2);
            a3 = fmaf(wreg[j+3].x, x3.x, a3); a3 = fmaf(wreg[j+3].y, x3.y, a3);
            a3 = fmaf(wreg[j+3].z, x3.z, a3); a3 = fmaf(wreg[j+3].w, x3.w, a3);
        }
        float acc = (a0 + a1) + (a2 + a3);
        #pragma unroll
        for (int off = 16; off > 0; off >>= 1)
            acc += __shfl_xor_sync(0xffffffffu, acc, off);

        if (lane == 0) {
            const float val = tanhf(fmaf(my_win, uk, acc));
            st_cg_f32(&g_x[buf ^ 1][row], val);   // publish slice (weak)
            if (k >= WASHOUT)
                part_row[k - WASHOUT] = val * my_coef;
        }
        __syncthreads();                          // all 8 slices stored (hb)
        if (tid == 0)
            st_rel_u32(&g_flag[buf ^ 1][cta][0], want + 1u);  // release flag
    }
}

// ---------------------------------------------------------------------------
// Finalize: deterministic fixed-order reduction of 1024 per-row partials.
// ---------------------------------------------------------------------------
__global__ void esn_finalize(float* __restrict__ out) {
    int t = blockIdx.x * blockDim.x + threadIdx.x;
    if (t < NOUT) {
        float s = 0.0f;
        #pragma unroll 8
        for (int r = 0; r < NPART; ++r)
            s += g_part[(size_t)r * NOUT + t];    // coalesced across threads
        out[t] = s;
    }
}

// ---------------------------------------------------------------------------
// Inputs (metadata order): u[50000] f32, w_in[1024] f32, w_res[1024*1024] f32,
// w_out[1024] f32, w_out_mask[1024] int (32/64 probed). Output: 49800 f32.
// ---------------------------------------------------------------------------
extern "C" void kernel_launch(void* const* d_in, const int* in_sizes, int n_in,
                              void* d_out, int out_size) {
    const float* u     = (const float*)d_in[0];
    const float* w_in  = (const float*)d_in[1];
    const float* w_res = (const float*)d_in[2];
    const float* w_out = (const float*)d_in[3];
    const void*  mask  = d_in[4];
    float*       out   = (float*)d_out;

    esn_prologue<<<1, 1024>>>(w_out, mask);
    esn_main<<<B, THREADS>>>(u, w_in, w_res);
    esn_finalize<<<(NOUT + 255) / 256, 256>>>(out);
}

// round 6
// speedup vs baseline: 1.9271x; 1.1684x over previous
#include <cuda_runtime.h>

// ESN recurrence on GB300 — single-hop exchange: each x element published as
// one atomic tagged u64 {tag<<32 | f32bits} via st.release.gpu. Consumers poll
// ONE acquire anchor per thread (acquires serialize -> never chain them), then
// validate their remaining 3 words with parallel scalar weak loads, each
// self-validated by its own tag.

#define H        1024
#define T        50000
#define WASHOUT  200
#define NOUT     (T - WASHOUT)   // 49800
#define B        128             // CTAs (<=148 SMs -> co-resident, spin-safe)
#define R        (H / B)         // 8 rows per CTA
#define THREADS  256             // 8 warps, 1 warp per row
#define NPART    (B * R)         // 1024 partial rows

// Tagged state grouped by producer CTA: one 128B line per (buffer, producer).
__device__ __align__(128) unsigned long long g_xt[2][B][16];  // [0..7] used
__device__ float    g_coef[H];                    // coef[mask[h]] = w_out[h]
__device__ unsigned g_epoch;                      // bumped per replay
__device__ float    g_part[(size_t)NPART * NOUT]; // per-row readout partials

static __device__ __forceinline__ unsigned long long pack_tv(unsigned tag, float v) {
    return ((unsigned long long)tag << 32) | (unsigned long long)__float_as_uint(v);
}
static __device__ __forceinline__ unsigned long long ld_acq_u64(const unsigned long long* p) {
    unsigned long long v;
    asm volatile("ld.acquire.gpu.global.u64 %0, [%1];" : "=l"(v) : "l"(p) : "memory");
    return v;
}
static __device__ __forceinline__ unsigned long long ld_cg_u64(const unsigned long long* p) {
    unsigned long long v;
    asm volatile("ld.global.cg.u64 %0, [%1];" : "=l"(v) : "l"(p) : "memory");
    return v;
}
static __device__ __forceinline__ void st_rel_u64(unsigned long long* p, unsigned long long v) {
    asm volatile("st.release.gpu.global.u64 [%0], %1;" :: "l"(p), "l"(v) : "memory");
}

// ---------------------------------------------------------------------------
// Prologue: bump epoch, publish x0 = 0 (tag = base), build coef scatter.
// Mask dtype probed in parallel (int64 has >=512 zero odd int32 slots).
// ---------------------------------------------------------------------------
__global__ void esn_prologue(const float* __restrict__ w_out,
                             const void* __restrict__ mask_raw) {
    const int* m32 = (const int*)mask_raw;
    const int t = threadIdx.x;                    // 0..1023

    int is64 = __syncthreads_count(((t & 1) != 0) && (m32[t] == 0)) >= 256;
    if (t == 0) g_epoch = g_epoch + 1u;
    __syncthreads();
    const unsigned base = g_epoch * (unsigned)(T + 2);

    int idx;
    if (is64) idx = (int)((const long long*)mask_raw)[t];
    else      idx = m32[t];
    g_coef[idx & 1023] = w_out[t];
    g_xt[0][t >> 3][t & 7] = pack_tv(base, 0.0f); // x_0 = 0, tag = base
}

// ---------------------------------------------------------------------------
// Main persistent kernel. Warp w of CTA c owns row c*8+w (weights in regs).
// Thread t consumes words [w0..w0+3] of producer p = t/2 (w0 = (t&1)*4):
//   acquire-poll word w0 until tag matches, weak-validate w0+1..3 (parallel),
//   stage float4 to SMEM, bar, reg-weight dot, shfl reduce, tanh,
//   lane0 release-publishes ONE tagged word, bar.
// ---------------------------------------------------------------------------
__global__ void __launch_bounds__(THREADS, 1)
esn_main(const float* __restrict__ u,
         const float* __restrict__ w_in,
         const float* __restrict__ w_res) {
    __shared__ float s_x[H];                      // 4 KB staging

    const int tid  = threadIdx.x;
    const int warp = tid >> 5;
    const int lane = tid & 31;
    const int cta  = blockIdx.x;
    const int row  = cta * R + warp;
    const int p    = tid >> 1;                    // producer CTA of my float4
    const int w0   = (tid & 1) * 4;               // word offset within its line

    // Weights into registers: lane l holds cols 4l+128j, j=0..7 (32 floats)
    float4 wreg[8];
    {
        const float4* wr = reinterpret_cast<const float4*>(w_res + (size_t)row * H);
        #pragma unroll
        for (int j = 0; j < 8; ++j)
            wreg[j] = __ldg(wr + lane + 32 * j);
    }
    const float my_win  = w_in[row];
    const float my_coef = g_coef[row];
    const unsigned base = g_epoch * (unsigned)(T + 2);
    float* part_row = &g_part[(size_t)row * NOUT];

    const unsigned long long* gx[2] = { &g_xt[0][p][w0], &g_xt[1][p][w0] };

    for (int k = 0; k < T; ++k) {
        const float uk = __ldg(u + k);            // issues early, used at tanh
        const unsigned want = base + (unsigned)k;
        const int buf = k & 1;
        const unsigned long long* g = gx[buf];

        // ---- poll: ONE acquire anchor (acquires serialize; never chain) ----
        unsigned long long v0;
        do { v0 = ld_acq_u64(g); } while ((unsigned)(v0 >> 32) != want);

        // ---- validate remaining 3 words: parallel weak loads, self-tagged --
        unsigned long long v1, v2, v3;
        for (;;) {
            v1 = ld_cg_u64(g + 1);
            v2 = ld_cg_u64(g + 2);
            v3 = ld_cg_u64(g + 3);
            if ((unsigned)(v1 >> 32) == want &&
                (unsigned)(v2 >> 32) == want &&
                (unsigned)(v3 >> 32) == want) break;
        }

        float4 xv;
        xv.x = __uint_as_float((unsigned)v0);
        xv.y = __uint_as_float((unsigned)v1);
        xv.z = __uint_as_float((unsigned)v2);
        xv.w = __uint_as_float((unsigned)v3);
        reinterpret_cast<float4*>(s_x)[tid] = xv;
        __syncthreads();                          // all 1024 values staged

        // ---- register-weight dot product (4 accumulators) ------------------
        const float4* xr = reinterpret_cast<const float4*>(s_x);
        float a0 = 0.f, a1 = 0.f, a2 = 0.f, a3 = 0.f;
        #pragma unroll
        for (int j = 0; j < 8; j += 4) {
            float4 x0 = xr[lane + 32 * (j + 0)];
            float4 x1 = xr[lane + 32 * (j + 1)];
            float4 x2 = xr[lane + 32 * (j + 2)];
            float4 x3 = xr[lane + 32 * (j + 3)];
            a0 = fmaf(wreg[j+0].x, x0.x, a0); a0 = fmaf(wreg[j+0].y, x0.y, a0);
            a0 = fmaf(wreg[j+0].z, x0.z, a0); a0 = fmaf(wreg[j+0].w, x0.w, a0);
            a1 = fmaf(wreg[j+1].x, x1.x, a1); a1 = fmaf(wreg[j+1].y, x1.y, a1);
            a1 = fmaf(wreg[j+1].z, x1.z, a1); a1 = fmaf(wreg[j+1].w, x1.w, a1);
            a2 = fmaf(wreg[j+2].x, x2.x, a2); a2 = fmaf(wreg[j+2].y, x2.y, a2);
            a2 = fmaf(wreg[j+2].z, x2.z, a2); a2 = fmaf(wreg[j+2].w, x2.w, a2);
            a3 = fmaf(wreg[j+3].x, x3.x, a3); a3 = fmaf(wreg[j+3].y, x3.y, a3);
            a3 = fmaf(wreg[j+3].z, x3.z, a3); a3 = fmaf(wreg[j+3].w, x3.w, a3);
        }
        float acc = (a0 + a1) + (a2 + a3);
        #pragma unroll
        for (int off = 16; off > 0; off >>= 1)
            acc += __shfl_xor_sync(0xffffffffu, acc, off);

        if (lane == 0) {
            const float val = tanhf(fmaf(my_win, uk, acc));
            // single-hop publish: tag + value atomic in one 8B release store
            st_rel_u64(&g_xt[buf ^ 1][cta][warp], pack_tv(want + 1u, val));
            if (k >= WASHOUT)
                part_row[k - WASHOUT] = val * my_coef;
        }
        __syncthreads();                          // protect s_x reuse next step
    }
}

// ---------------------------------------------------------------------------
// Finalize: deterministic fixed-order reduction of 1024 per-row partials.
// ---------------------------------------------------------------------------
__global__ void esn_finalize(float* __restrict__ out) {
    int t = blockIdx.x * blockDim.x + threadIdx.x;
    if (t < NOUT) {
        float s = 0.0f;
        #pragma unroll 8
        for (int r = 0; r < NPART; ++r)
            s += g_part[(size_t)r * NOUT + t];    // coalesced across threads
        out[t] = s;
    }
}

// ---------------------------------------------------------------------------
// Inputs (metadata order): u[50000] f32, w_in[1024] f32, w_res[1024*1024] f32,
// w_out[1024] f32, w_out_mask[1024] int (32/64 probed). Output: 49800 f32.
// ---------------------------------------------------------------------------
extern "C" void kernel_launch(void* const* d_in, const int* in_sizes, int n_in,
                              void* d_out, int out_size) {
    const float* u     = (const float*)d_in[0];
    const float* w_in  = (const float*)d_in[1];
    const float* w_res = (const float*)d_in[2];
    const float* w_out = (const float*)d_in[3];
    const void*  mask  = d_in[4];
    float*       out   = (float*)d_out;

    esn_prologue<<<1, 1024>>>(w_out, mask);
    esn_main<<<B, THREADS>>>(u, w_in, w_res);
    esn_finalize<<<(NOUT + 255) / 256, 256>>>(out);
}